// round 1
// baseline (speedup 1.0000x reference)
#include <cuda_runtime.h>
#include <math.h>

// Problem dims (fixed by the dataset)
#define BDIM 4096   // batch (M)
#define DDIM 2048   // output dim (N)
#define KDIM 2048   // inner dim (K)

// -------- device scratch (no cudaMalloc allowed) --------
__device__ int   g_flags[2];                  // [0]: mem0 has nonzero, [1]: out0 has nonzero
__device__ float g_preA[BDIM * DDIM];         // pre-activation of block_inp
__device__ float g_preB[BDIM * DDIM];         // pre-activation of inp_gate
__device__ float g_preC[BDIM * DDIM];         // pre-activation of read_gate (then rg*mem0 in place)
__device__ float g_dec [BDIM * DDIM];         // decoded_mem

__device__ __forceinline__ float sigmoidf_(float v) {
    return 1.0f / (1.0f + expf(-v));
}

// -------- flag reset + nonzero scan --------
__global__ void reset_flags_kernel() {
    g_flags[0] = 0;
    g_flags[1] = 0;
}

__global__ void scan_kernel(const float4* __restrict__ m4,
                            const float4* __restrict__ o4) {
    const int total = (BDIM * DDIM) / 4;
    bool nzm = false, nzo = false;
    for (int i = blockIdx.x * blockDim.x + threadIdx.x; i < total;
         i += gridDim.x * blockDim.x) {
        float4 v = m4[i];
        nzm |= (v.x != 0.0f) | (v.y != 0.0f) | (v.z != 0.0f) | (v.w != 0.0f);
        float4 u = o4[i];
        nzo |= (u.x != 0.0f) | (u.y != 0.0f) | (u.z != 0.0f) | (u.w != 0.0f);
    }
    if (nzm) atomicOr(&g_flags[0], 1);
    if (nzo) atomicOr(&g_flags[1], 1);
}

// -------- SGEMM: C[m][n] (+)= sum_k A[m][k] * W[n][k]  (+ up to 3 biases on init) --------
// 128x128 tile, BK=16, 256 threads, 8x8 register tile per thread.
// flagsel bit0: require g_flags[0] (mem0 nonzero); bit1: require g_flags[1] (out0 nonzero)
__global__ __launch_bounds__(256)
void sgemm_nt(const float* __restrict__ A, const float* __restrict__ W,
              float* __restrict__ C,
              const float* __restrict__ b0, const float* __restrict__ b1,
              const float* __restrict__ b2,
              int flagsel, int accum)
{
    if ((flagsel & 1) && g_flags[0] == 0) return;
    if ((flagsel & 2) && g_flags[1] == 0) return;

    __shared__ float As[16][128];
    __shared__ float Ws[16][128];

    const int t  = threadIdx.x;
    const int tx = t & 15;        // 0..15 (n direction)
    const int ty = t >> 4;        // 0..15 (m direction)
    const int bm = blockIdx.y * 128;
    const int bn = blockIdx.x * 128;
    const int lr = t >> 2;        // 0..63 : row within tile for loads
    const int lk = (t & 3) << 2;  // 0,4,8,12 : k offset for loads

    const float* Ap = A + (size_t)(bm + lr) * KDIM + lk;
    const float* Wp = W + (size_t)(bn + lr) * KDIM + lk;

    float acc[8][8];
    #pragma unroll
    for (int i = 0; i < 8; i++)
        #pragma unroll
        for (int j = 0; j < 8; j++)
            acc[i][j] = 0.0f;

    for (int kt = 0; kt < KDIM; kt += 16) {
        float4 a0 = *(const float4*)(Ap + kt);
        float4 a1 = *(const float4*)(Ap + (size_t)64 * KDIM + kt);
        float4 w0 = *(const float4*)(Wp + kt);
        float4 w1 = *(const float4*)(Wp + (size_t)64 * KDIM + kt);

        __syncthreads();  // previous iter's compute must be done before overwrite
        As[lk + 0][lr] = a0.x; As[lk + 1][lr] = a0.y;
        As[lk + 2][lr] = a0.z; As[lk + 3][lr] = a0.w;
        As[lk + 0][lr + 64] = a1.x; As[lk + 1][lr + 64] = a1.y;
        As[lk + 2][lr + 64] = a1.z; As[lk + 3][lr + 64] = a1.w;
        Ws[lk + 0][lr] = w0.x; Ws[lk + 1][lr] = w0.y;
        Ws[lk + 2][lr] = w0.z; Ws[lk + 3][lr] = w0.w;
        Ws[lk + 0][lr + 64] = w1.x; Ws[lk + 1][lr + 64] = w1.y;
        Ws[lk + 2][lr + 64] = w1.z; Ws[lk + 3][lr + 64] = w1.w;
        __syncthreads();

        #pragma unroll
        for (int k = 0; k < 16; k++) {
            float4 am0 = *(const float4*)&As[k][ty * 4];
            float4 am1 = *(const float4*)&As[k][ty * 4 + 64];
            float4 wn0 = *(const float4*)&Ws[k][tx * 4];
            float4 wn1 = *(const float4*)&Ws[k][tx * 4 + 64];
            float am[8] = {am0.x, am0.y, am0.z, am0.w, am1.x, am1.y, am1.z, am1.w};
            float wn[8] = {wn0.x, wn0.y, wn0.z, wn0.w, wn1.x, wn1.y, wn1.z, wn1.w};
            #pragma unroll
            for (int i = 0; i < 8; i++)
                #pragma unroll
                for (int j = 0; j < 8; j++)
                    acc[i][j] = fmaf(am[i], wn[j], acc[i][j]);
        }
    }

    // ---- epilogue ----
    const int n0 = bn + tx * 4;
    float bias[8] = {0, 0, 0, 0, 0, 0, 0, 0};
    if (!accum) {
        #pragma unroll
        for (int j = 0; j < 4; j++) {
            float s0 = 0.0f, s1 = 0.0f;
            if (b0) { s0 += b0[n0 + j]; s1 += b0[n0 + 64 + j]; }
            if (b1) { s0 += b1[n0 + j]; s1 += b1[n0 + 64 + j]; }
            if (b2) { s0 += b2[n0 + j]; s1 += b2[n0 + 64 + j]; }
            bias[j] = s0; bias[4 + j] = s1;
        }
    }

    #pragma unroll
    for (int ii = 0; ii < 8; ii++) {
        int m = bm + ty * 4 + (ii & 3) + ((ii & 4) ? 64 : 0);
        float* crow = C + (size_t)m * DDIM;
        float4 v0 = make_float4(acc[ii][0] + bias[0], acc[ii][1] + bias[1],
                                acc[ii][2] + bias[2], acc[ii][3] + bias[3]);
        float4 v1 = make_float4(acc[ii][4] + bias[4], acc[ii][5] + bias[5],
                                acc[ii][6] + bias[6], acc[ii][7] + bias[7]);
        if (accum) {
            float4 c0 = *(const float4*)(crow + n0);
            float4 c1 = *(const float4*)(crow + n0 + 64);
            v0.x += c0.x; v0.y += c0.y; v0.z += c0.z; v0.w += c0.w;
            v1.x += c1.x; v1.y += c1.y; v1.z += c1.z; v1.w += c1.w;
        }
        *(float4*)(crow + n0)      = v0;
        *(float4*)(crow + n0 + 64) = v1;
    }
}

// -------- read_gate * mem0 (in place into g_preC), gated on mem0 nonzero --------
__global__ void rgmem_kernel(const float* __restrict__ mem0) {
    if (g_flags[0] == 0) return;
    const int total = BDIM * DDIM;
    for (int i = blockIdx.x * blockDim.x + threadIdx.x; i < total;
         i += gridDim.x * blockDim.x) {
        g_preC[i] = sigmoidf_(g_preC[i]) * mem0[i];
    }
}

// -------- final: out = decoded_mem + sigmoid(preA) * sigmoid(preB) --------
__global__ void final_kernel(float* __restrict__ out,
                             const float* __restrict__ b_dec) {
    const bool usemem = (g_flags[0] != 0);
    const int total = BDIM * DDIM;
    for (int i = blockIdx.x * blockDim.x + threadIdx.x; i < total;
         i += gridDim.x * blockDim.x) {
        float d = usemem ? g_dec[i] : b_dec[i & (DDIM - 1)];
        out[i] = d + sigmoidf_(g_preA[i]) * sigmoidf_(g_preB[i]);
    }
}

extern "C" void kernel_launch(void* const* d_in, const int* in_sizes, int n_in,
                              void* d_out, int out_size) {
    // Input order per setup_inputs(): x, out0, mem0, then (w,b) per NAMES
    const float* x              = (const float*)d_in[0];
    const float* out0           = (const float*)d_in[1];
    const float* mem0           = (const float*)d_in[2];
    const float* w_inpgate      = (const float*)d_in[3];
    const float* b_inpgate      = (const float*)d_in[4];
    const float* w_rec_inpgate  = (const float*)d_in[5];
    const float* b_rec_inpgate  = (const float*)d_in[6];
    const float* w_mem_inpgate  = (const float*)d_in[7];
    const float* b_mem_inpgate  = (const float*)d_in[8];
    const float* w_inp          = (const float*)d_in[9];
    const float* b_inp          = (const float*)d_in[10];
    const float* w_rec_inp      = (const float*)d_in[11];
    const float* b_rec_inp      = (const float*)d_in[12];
    const float* w_readgate     = (const float*)d_in[13];
    const float* b_readgate     = (const float*)d_in[14];
    const float* w_rec_readgate = (const float*)d_in[15];
    const float* b_rec_readgate = (const float*)d_in[16];
    const float* w_mem_readgate = (const float*)d_in[17];
    const float* b_mem_readgate = (const float*)d_in[18];
    const float* w_decoder      = (const float*)d_in[19];
    const float* b_decoder      = (const float*)d_in[20];
    // indices 21..28 (writegate/encoder) do not affect the returned `hidden`
    float* out = (float*)d_out;

    void *pA, *pB, *pC, *pD;
    cudaGetSymbolAddress(&pA, g_preA);
    cudaGetSymbolAddress(&pB, g_preB);
    cudaGetSymbolAddress(&pC, g_preC);
    cudaGetSymbolAddress(&pD, g_dec);
    float* preA = (float*)pA;
    float* preB = (float*)pB;
    float* preC = (float*)pC;
    float* dec  = (float*)pD;

    dim3 blk(256);
    dim3 grid(DDIM / 128, BDIM / 128);  // 16 x 32 CTAs

    // 1) flags: does mem0 / out0 contain any nonzero?
    reset_flags_kernel<<<1, 1>>>();
    scan_kernel<<<2048, 256>>>((const float4*)mem0, (const float4*)out0);

    // 2) preA = x@Wi^T + b_inp + b_rec_inp  (+ out0@Wri^T if out0 != 0)
    sgemm_nt<<<grid, blk>>>(x,    w_inp,     preA, b_inp, b_rec_inp, nullptr, 0, 0);
    sgemm_nt<<<grid, blk>>>(out0, w_rec_inp, preA, nullptr, nullptr, nullptr, 2, 1);

    // 3) preB = x@Wig^T + all three gate biases (+ mem0 / out0 terms if nonzero)
    sgemm_nt<<<grid, blk>>>(x,    w_inpgate,     preB, b_inpgate, b_mem_inpgate, b_rec_inpgate, 0, 0);
    sgemm_nt<<<grid, blk>>>(mem0, w_mem_inpgate, preB, nullptr, nullptr, nullptr, 1, 1);
    sgemm_nt<<<grid, blk>>>(out0, w_rec_inpgate, preB, nullptr, nullptr, nullptr, 2, 1);

    // 4) preC (read_gate pre-act) — only relevant when mem0 != 0
    sgemm_nt<<<grid, blk>>>(x,    w_readgate,     preC, b_readgate, b_mem_readgate, b_rec_readgate, 1, 0);
    sgemm_nt<<<grid, blk>>>(mem0, w_mem_readgate, preC, nullptr, nullptr, nullptr, 1, 1);
    sgemm_nt<<<grid, blk>>>(out0, w_rec_readgate, preC, nullptr, nullptr, nullptr, 3, 1);

    // 5) preC = sigmoid(preC) * mem0  (gated on mem0 nonzero)
    rgmem_kernel<<<4096, 256>>>(mem0);

    // 6) dec = (read_gate*mem0)@Wdec^T + b_decoder  (gated on mem0 nonzero)
    sgemm_nt<<<grid, blk>>>(preC, w_decoder, dec, b_decoder, nullptr, nullptr, 1, 0);

    // 7) out = dec(or b_decoder) + sigmoid(preA)*sigmoid(preB)
    final_kernel<<<4096, 256>>>(out, b_decoder);
}

// round 3
// speedup vs baseline: 3.0770x; 3.0770x over previous
#include <cuda_runtime.h>
#include <cstdint>
#include <math.h>

#define BDIM 4096
#define DDIM 2048
#define KDIM 2048

// ---------------- device scratch (no cudaMalloc allowed) ----------------
__device__ int   g_flags[2];              // [0] mem0 nonzero, [1] out0 nonzero
__device__ float g_preA[BDIM * DDIM];
__device__ float g_preB[BDIM * DDIM];
__device__ float g_preC[BDIM * DDIM];
__device__ float g_dec [BDIM * DDIM];
__device__ float g_ax  [BDIM * KDIM];     // tf32-rounded x
__device__ float g_ay  [BDIM * KDIM];     // tf32-rounded out0/mem0/preC (reused)
__device__ float g_w   [DDIM * KDIM];     // tf32-rounded current weight (reused)

__device__ __forceinline__ float sigmoidf_(float v) { return 1.0f / (1.0f + expf(-v)); }

__device__ __forceinline__ uint32_t smem_to_u32(const void* p) {
    uint32_t a;
    asm("{ .reg .u64 t; cvta.to.shared.u64 t, %1; cvt.u32.u64 %0, t; }" : "=r"(a) : "l"(p));
    return a;
}

__device__ __forceinline__ void cp16(uint32_t dst, const void* src) {
    asm volatile("cp.async.cg.shared.global [%0], [%1], 16;" :: "r"(dst), "l"(src) : "memory");
}
#define CP_COMMIT() asm volatile("cp.async.commit_group;" ::: "memory")

__device__ __forceinline__ float tf32_rna(float v) {
    uint32_t o;
    asm("cvt.rna.tf32.f32 %0, %1;" : "=r"(o) : "f"(v));
    return __uint_as_float(o);
}

__device__ __forceinline__ void mma_tf32(float& c0, float& c1, float& c2, float& c3,
                                         uint32_t a0, uint32_t a1, uint32_t a2, uint32_t a3,
                                         uint32_t b0, uint32_t b1) {
    asm volatile("mma.sync.aligned.m16n8k8.row.col.f32.tf32.tf32.f32 "
                 "{%0,%1,%2,%3}, {%4,%5,%6,%7}, {%8,%9}, {%0,%1,%2,%3};"
                 : "+f"(c0), "+f"(c1), "+f"(c2), "+f"(c3)
                 : "r"(a0), "r"(a1), "r"(a2), "r"(a3), "r"(b0), "r"(b1));
}

// ---------------- flags + scan ----------------
__global__ void reset_flags_kernel() { g_flags[0] = 0; g_flags[1] = 0; }

__global__ void scan_kernel(const float4* __restrict__ m4, const float4* __restrict__ o4) {
    const int total = (BDIM * DDIM) / 4;
    bool nzm = false, nzo = false;
    for (int i = blockIdx.x * blockDim.x + threadIdx.x; i < total; i += gridDim.x * blockDim.x) {
        float4 v = m4[i];
        nzm |= (v.x != 0.0f) | (v.y != 0.0f) | (v.z != 0.0f) | (v.w != 0.0f);
        float4 u = o4[i];
        nzo |= (u.x != 0.0f) | (u.y != 0.0f) | (u.z != 0.0f) | (u.w != 0.0f);
    }
    if (nzm) atomicOr(&g_flags[0], 1);
    if (nzo) atomicOr(&g_flags[1], 1);
}

// ---------------- fp32 -> tf32 (round-to-nearest) ----------------
__global__ void round_kernel(const float4* __restrict__ src, float4* __restrict__ dst,
                             int n4, int flagsel) {
    if ((flagsel & 1) && g_flags[0] == 0) return;
    if ((flagsel & 2) && g_flags[1] == 0) return;
    for (int i = blockIdx.x * blockDim.x + threadIdx.x; i < n4; i += gridDim.x * blockDim.x) {
        float4 v = src[i];
        v.x = tf32_rna(v.x); v.y = tf32_rna(v.y);
        v.z = tf32_rna(v.z); v.w = tf32_rna(v.w);
        dst[i] = v;
    }
}

// ---------------- TF32 mma.sync GEMM ----------------
// C[m][n] (+)= sum_k A[m][k] * W[n][k]   (A,W pre-rounded to tf32)
// CTA tile 128(M) x 256(N) x 32(K); 8 warps = 2(M) x 4(N), warp tile 64x64.
#define BK 32
#define CHUNKS (KDIM / BK)
#define CTAM 128
#define CTAN 256
#define ROWSTRIDE 36                       // 32 + 4 pad floats
#define A_FLOATS (CTAM * ROWSTRIDE)        // 4608
#define B_FLOATS (CTAN * ROWSTRIDE)        // 9216
#define STAGE_FLOATS (A_FLOATS + B_FLOATS) // 13824
#define GEMM_SMEM (2 * STAGE_FLOATS * 4)   // 110592 bytes

__global__ __launch_bounds__(256, 1)
void gemm_tf32(const float* __restrict__ A, const float* __restrict__ W,
               float* __restrict__ C,
               const float* __restrict__ b0, const float* __restrict__ b1,
               const float* __restrict__ b2,
               int flagsel, int accum)
{
    if ((flagsel & 1) && g_flags[0] == 0) return;
    if ((flagsel & 2) && g_flags[1] == 0) return;

    extern __shared__ float smem[];
    const uint32_t smem_u32 = smem_to_u32(smem);

    const int tid = threadIdx.x;
    const int wid = tid >> 5;
    const int lane = tid & 31;
    const int g = lane >> 2;      // groupID 0..7
    const int t = lane & 3;       // thread-in-group 0..3
    const int wm = wid & 1;       // warp M index (0..1)
    const int wn = wid >> 1;      // warp N index (0..3)
    const int bm = blockIdx.y * CTAM;
    const int bn = blockIdx.x * CTAN;

    float c[4][8][4];
    #pragma unroll
    for (int i = 0; i < 4; i++)
        #pragma unroll
        for (int j = 0; j < 8; j++)
            #pragma unroll
            for (int q = 0; q < 4; q++) c[i][j][q] = 0.0f;

    // ---- async tile loader (16B granules, padded rows) ----
    auto load_chunk = [&](int stage, int kt) {
        const uint32_t sb = smem_u32 + (uint32_t)stage * STAGE_FLOATS * 4;
        // A: 128 rows x 8 granules = 1024
        #pragma unroll
        for (int i = 0; i < 4; i++) {
            int gr = tid + i * 256;
            int row = gr >> 3, c4 = gr & 7;
            cp16(sb + (uint32_t)(row * ROWSTRIDE + c4 * 4) * 4,
                 A + (size_t)(bm + row) * KDIM + kt + c4 * 4);
        }
        // W: 256 rows x 8 granules = 2048
        #pragma unroll
        for (int i = 0; i < 8; i++) {
            int gr = tid + i * 256;
            int row = gr >> 3, c4 = gr & 7;
            cp16(sb + (uint32_t)(A_FLOATS + row * ROWSTRIDE + c4 * 4) * 4,
                 W + (size_t)(bn + row) * KDIM + kt + c4 * 4);
        }
        CP_COMMIT();
    };

    load_chunk(0, 0);

    for (int ch = 0; ch < CHUNKS; ch++) {
        if (ch + 1 < CHUNKS) {
            load_chunk((ch + 1) & 1, (ch + 1) * BK);
            asm volatile("cp.async.wait_group 1;" ::: "memory");
        } else {
            asm volatile("cp.async.wait_group 0;" ::: "memory");
        }
        __syncthreads();

        const uint32_t* As = (const uint32_t*)(smem + (ch & 1) * STAGE_FLOATS);
        const uint32_t* Bs = As + A_FLOATS;

        #pragma unroll
        for (int s = 0; s < 4; s++) {
            const int k0 = s * 8;
            uint32_t a[4][4];
            #pragma unroll
            for (int mf = 0; mf < 4; mf++) {
                const int r0 = wm * 64 + mf * 16 + g;
                a[mf][0] = As[r0 * ROWSTRIDE + k0 + t];
                a[mf][1] = As[(r0 + 8) * ROWSTRIDE + k0 + t];
                a[mf][2] = As[r0 * ROWSTRIDE + k0 + t + 4];
                a[mf][3] = As[(r0 + 8) * ROWSTRIDE + k0 + t + 4];
            }
            uint32_t b[8][2];
            #pragma unroll
            for (int nf = 0; nf < 8; nf++) {
                const int n0 = wn * 64 + nf * 8 + g;
                b[nf][0] = Bs[n0 * ROWSTRIDE + k0 + t];
                b[nf][1] = Bs[n0 * ROWSTRIDE + k0 + t + 4];
            }
            #pragma unroll
            for (int mf = 0; mf < 4; mf++)
                #pragma unroll
                for (int nf = 0; nf < 8; nf++)
                    mma_tf32(c[mf][nf][0], c[mf][nf][1], c[mf][nf][2], c[mf][nf][3],
                             a[mf][0], a[mf][1], a[mf][2], a[mf][3],
                             b[nf][0], b[nf][1]);
        }
        __syncthreads();
    }

    // ---- epilogue ----
    #pragma unroll
    for (int nf = 0; nf < 8; nf++) {
        const int col = bn + wn * 64 + nf * 8 + 2 * t;
        float bs0 = 0.0f, bs1 = 0.0f;
        if (!accum) {
            if (b0) { bs0 += b0[col]; bs1 += b0[col + 1]; }
            if (b1) { bs0 += b1[col]; bs1 += b1[col + 1]; }
            if (b2) { bs0 += b2[col]; bs1 += b2[col + 1]; }
        }
        #pragma unroll
        for (int mf = 0; mf < 4; mf++) {
            const int r = bm + wm * 64 + mf * 16 + g;
            float2 v0 = make_float2(c[mf][nf][0] + bs0, c[mf][nf][1] + bs1);
            float2 v1 = make_float2(c[mf][nf][2] + bs0, c[mf][nf][3] + bs1);
            float2* p0 = (float2*)(C + (size_t)r * DDIM + col);
            float2* p1 = (float2*)(C + (size_t)(r + 8) * DDIM + col);
            if (accum) {
                float2 o0 = *p0, o1 = *p1;
                v0.x += o0.x; v0.y += o0.y; v1.x += o1.x; v1.y += o1.y;
            }
            *p0 = v0;
            *p1 = v1;
        }
    }
}

// ---------------- elementwise ----------------
__global__ void rgmem_kernel(const float* __restrict__ mem0) {
    if (g_flags[0] == 0) return;
    const int total = BDIM * DDIM;
    for (int i = blockIdx.x * blockDim.x + threadIdx.x; i < total; i += gridDim.x * blockDim.x)
        g_preC[i] = sigmoidf_(g_preC[i]) * mem0[i];
}

__global__ void final_kernel(float* __restrict__ out, const float* __restrict__ b_dec) {
    const bool usemem = (g_flags[0] != 0);
    const int total = BDIM * DDIM;
    for (int i = blockIdx.x * blockDim.x + threadIdx.x; i < total; i += gridDim.x * blockDim.x) {
        float d = usemem ? g_dec[i] : b_dec[i & (DDIM - 1)];
        out[i] = d + sigmoidf_(g_preA[i]) * sigmoidf_(g_preB[i]);
    }
}

// ---------------- host orchestration ----------------
extern "C" void kernel_launch(void* const* d_in, const int* in_sizes, int n_in,
                              void* d_out, int out_size) {
    const float* x              = (const float*)d_in[0];
    const float* out0           = (const float*)d_in[1];
    const float* mem0           = (const float*)d_in[2];
    const float* w_inpgate      = (const float*)d_in[3];
    const float* b_inpgate      = (const float*)d_in[4];
    const float* w_rec_inpgate  = (const float*)d_in[5];
    const float* b_rec_inpgate  = (const float*)d_in[6];
    const float* w_mem_inpgate  = (const float*)d_in[7];
    const float* b_mem_inpgate  = (const float*)d_in[8];
    const float* w_inp          = (const float*)d_in[9];
    const float* b_inp          = (const float*)d_in[10];
    const float* w_rec_inp      = (const float*)d_in[11];
    const float* b_rec_inp      = (const float*)d_in[12];
    const float* w_readgate     = (const float*)d_in[13];
    const float* b_readgate     = (const float*)d_in[14];
    const float* w_rec_readgate = (const float*)d_in[15];
    const float* b_rec_readgate = (const float*)d_in[16];
    const float* w_mem_readgate = (const float*)d_in[17];
    const float* b_mem_readgate = (const float*)d_in[18];
    const float* w_decoder      = (const float*)d_in[19];
    const float* b_decoder      = (const float*)d_in[20];
    float* out = (float*)d_out;

    void *pA, *pB, *pC, *pD, *pax, *pay, *pw;
    cudaGetSymbolAddress(&pA, g_preA); cudaGetSymbolAddress(&pB, g_preB);
    cudaGetSymbolAddress(&pC, g_preC); cudaGetSymbolAddress(&pD, g_dec);
    cudaGetSymbolAddress(&pax, g_ax);  cudaGetSymbolAddress(&pay, g_ay);
    cudaGetSymbolAddress(&pw, g_w);
    float* preA = (float*)pA;  float* preB = (float*)pB;
    float* preC = (float*)pC;  float* dec  = (float*)pD;
    float* ax = (float*)pax;   float* ay = (float*)pay;   float* wbuf = (float*)pw;

    cudaFuncSetAttribute(gemm_tf32, cudaFuncAttributeMaxDynamicSharedMemorySize, GEMM_SMEM);

    const int nA4 = (BDIM * KDIM) / 4;
    const int nW4 = (DDIM * KDIM) / 4;
    dim3 gg(DDIM / CTAN, BDIM / CTAM);   // 8 x 32 = 256 CTAs

    #define ROUND(src, dst, n4, fl) \
        round_kernel<<<1024, 256>>>((const float4*)(src), (float4*)(dst), (n4), (fl))
    #define GEMM(Aop, Cc, B0, B1, B2, fl, acc) \
        gemm_tf32<<<gg, 256, GEMM_SMEM>>>((Aop), wbuf, (Cc), (B0), (B1), (B2), (fl), (acc))

    // 1) flags
    reset_flags_kernel<<<1, 1>>>();
    scan_kernel<<<2048, 256>>>((const float4*)mem0, (const float4*)out0);

    // 2) round x (always live)
    ROUND(x, ax, nA4, 0);

    // 3) preA = x@Wi^T + b_inp + b_rec_inp
    ROUND(w_inp, wbuf, nW4, 0);
    GEMM(ax, preA, b_inp, b_rec_inp, (const float*)nullptr, 0, 0);

    // 4) preB = x@Wig^T + gate biases
    ROUND(w_inpgate, wbuf, nW4, 0);
    GEMM(ax, preB, b_inpgate, b_mem_inpgate, b_rec_inpgate, 0, 0);

    // 5) preC = x@Wrg^T + biases        [mem0 != 0]
    ROUND(w_readgate, wbuf, nW4, 1);
    GEMM(ax, preC, b_readgate, b_mem_readgate, b_rec_readgate, 1, 0);

    // 6) out0 recurrent terms           [out0 != 0]
    ROUND(out0, ay, nA4, 2);
    ROUND(w_rec_inp, wbuf, nW4, 2);
    GEMM(ay, preA, (const float*)nullptr, (const float*)nullptr, (const float*)nullptr, 2, 1);
    ROUND(w_rec_inpgate, wbuf, nW4, 2);
    GEMM(ay, preB, (const float*)nullptr, (const float*)nullptr, (const float*)nullptr, 2, 1);
    ROUND(w_rec_readgate, wbuf, nW4, 3);
    GEMM(ay, preC, (const float*)nullptr, (const float*)nullptr, (const float*)nullptr, 3, 1);

    // 7) mem0 terms                     [mem0 != 0]
    ROUND(mem0, ay, nA4, 1);
    ROUND(w_mem_inpgate, wbuf, nW4, 1);
    GEMM(ay, preB, (const float*)nullptr, (const float*)nullptr, (const float*)nullptr, 1, 1);
    ROUND(w_mem_readgate, wbuf, nW4, 1);
    GEMM(ay, preC, (const float*)nullptr, (const float*)nullptr, (const float*)nullptr, 1, 1);

    // 8) read_gate * mem0, decoder GEMM [mem0 != 0]
    rgmem_kernel<<<4096, 256>>>(mem0);
    ROUND(preC, ay, nA4, 1);
    ROUND(w_decoder, wbuf, nW4, 1);
    GEMM(ay, dec, b_decoder, (const float*)nullptr, (const float*)nullptr, 1, 0);

    // 9) out = dec(or b_dec) + sig(preA)*sig(preB)
    final_kernel<<<4096, 256>>>(out, b_decoder);

    #undef ROUND
    #undef GEMM
}

// round 4
// speedup vs baseline: 5.0244x; 1.6329x over previous
#include <cuda_runtime.h>
#include <cuda_fp16.h>
#include <cstdint>
#include <math.h>

#define BDIM 4096
#define DDIM 2048
#define KDIM 2048

// ---------------- device scratch (no cudaMalloc allowed) ----------------
__device__ int    g_flags[2];              // [0] mem0 nonzero, [1] out0 nonzero
__device__ float  g_preA[BDIM * DDIM];
__device__ float  g_preB[BDIM * DDIM];
__device__ float  g_preC[BDIM * DDIM];
__device__ float  g_dec [BDIM * DDIM];
__device__ __half g_ax  [BDIM * KDIM];     // fp16 x
__device__ __half g_ay  [BDIM * KDIM];     // fp16 out0/mem0/preC (reused)
__device__ __half g_w0  [DDIM * KDIM];
__device__ __half g_w1  [DDIM * KDIM];
__device__ __half g_w2  [DDIM * KDIM];

struct GemmBatch {
    const __half* W[3];
    float*        C[3];
    const float*  b0[3];
    const float*  b1[3];
    const float*  b2[3];
    int           flagsel[3];   // bit0: need mem0!=0, bit1: need out0!=0
    int           accum;
};

struct ConvBatch {
    const float4* src[3];
    uint2*        dst[3];
    int           flagsel[3];
};

__device__ __forceinline__ float sigmoidf_(float v) { return 1.0f / (1.0f + expf(-v)); }

__device__ __forceinline__ uint32_t smem_to_u32(const void* p) {
    uint32_t a;
    asm("{ .reg .u64 t; cvta.to.shared.u64 t, %1; cvt.u32.u64 %0, t; }" : "=r"(a) : "l"(p));
    return a;
}

__device__ __forceinline__ void cp16(uint32_t dst, const void* src) {
    asm volatile("cp.async.cg.shared.global [%0], [%1], 16;" :: "r"(dst), "l"(src) : "memory");
}
#define CP_COMMIT() asm volatile("cp.async.commit_group;" ::: "memory")

__device__ __forceinline__ void mma_fp16(float& c0, float& c1, float& c2, float& c3,
                                         uint32_t a0, uint32_t a1, uint32_t a2, uint32_t a3,
                                         uint32_t b0, uint32_t b1) {
    asm volatile("mma.sync.aligned.m16n8k16.row.col.f32.f16.f16.f32 "
                 "{%0,%1,%2,%3}, {%4,%5,%6,%7}, {%8,%9}, {%0,%1,%2,%3};"
                 : "+f"(c0), "+f"(c1), "+f"(c2), "+f"(c3)
                 : "r"(a0), "r"(a1), "r"(a2), "r"(a3), "r"(b0), "r"(b1));
}

__device__ __forceinline__ bool flag_ok(int flagsel) {
    if ((flagsel & 1) && g_flags[0] == 0) return false;
    if ((flagsel & 2) && g_flags[1] == 0) return false;
    return true;
}

// ---------------- flags + scan ----------------
__global__ void reset_flags_kernel() { g_flags[0] = 0; g_flags[1] = 0; }

__global__ void scan_kernel(const float4* __restrict__ m4, const float4* __restrict__ o4) {
    const int total = (BDIM * DDIM) / 4;
    bool nzm = false, nzo = false;
    for (int i = blockIdx.x * blockDim.x + threadIdx.x; i < total; i += gridDim.x * blockDim.x) {
        float4 v = m4[i];
        nzm |= (v.x != 0.0f) | (v.y != 0.0f) | (v.z != 0.0f) | (v.w != 0.0f);
        float4 u = o4[i];
        nzo |= (u.x != 0.0f) | (u.y != 0.0f) | (u.z != 0.0f) | (u.w != 0.0f);
    }
    if (nzm) atomicOr(&g_flags[0], 1);
    if (nzo) atomicOr(&g_flags[1], 1);
}

// ---------------- fp32 -> fp16 conversion ----------------
__global__ void conv_kernel(const float4* __restrict__ src, uint2* __restrict__ dst,
                            int n4, int flagsel) {
    if (!flag_ok(flagsel)) return;
    for (int i = blockIdx.x * blockDim.x + threadIdx.x; i < n4; i += gridDim.x * blockDim.x) {
        float4 v = src[i];
        __half2 h0 = __floats2half2_rn(v.x, v.y);
        __half2 h1 = __floats2half2_rn(v.z, v.w);
        uint2 o;
        o.x = *(uint32_t*)&h0;
        o.y = *(uint32_t*)&h1;
        dst[i] = o;
    }
}

__global__ void convw_batch_kernel(ConvBatch cb, int n4) {
    const int z = blockIdx.z;
    if (!flag_ok(cb.flagsel[z])) return;
    const float4* __restrict__ src = cb.src[z];
    uint2* __restrict__ dst = cb.dst[z];
    for (int i = blockIdx.x * blockDim.x + threadIdx.x; i < n4; i += gridDim.x * blockDim.x) {
        float4 v = src[i];
        __half2 h0 = __floats2half2_rn(v.x, v.y);
        __half2 h1 = __floats2half2_rn(v.z, v.w);
        uint2 o;
        o.x = *(uint32_t*)&h0;
        o.y = *(uint32_t*)&h1;
        dst[i] = o;
    }
}

// ---------------- fp16 mma.sync GEMM ----------------
// C[m][n] (+)= sum_k A[m][k] * W[n][k]   (A,W fp16, fp32 accum)
// CTA tile 128(M) x 256(N) x 64(K); 8 warps = 2(M) x 4(N), warp tile 64x64.
#define BK 64
#define CHUNKS (KDIM / BK)                 // 32
#define CTAM 128
#define CTAN 256
#define STRH 72                            // 64 + 8 pad halves (144B rows)
#define A_HALVES (CTAM * STRH)             // 9216
#define B_HALVES (CTAN * STRH)             // 18432
#define STAGE_HALVES (A_HALVES + B_HALVES) // 27648
#define GEMM_SMEM (2 * STAGE_HALVES * 2)   // 110592 bytes

__global__ __launch_bounds__(256, 1)
void gemm_fp16(const __half* __restrict__ A, GemmBatch gb)
{
    const int z = blockIdx.z;
    if (!flag_ok(gb.flagsel[z])) return;
    const __half* __restrict__ W = gb.W[z];
    float* __restrict__ C = gb.C[z];

    extern __shared__ __half smem[];
    const uint32_t smem_u32 = smem_to_u32(smem);

    const int tid = threadIdx.x;
    const int wid = tid >> 5;
    const int lane = tid & 31;
    const int g = lane >> 2;
    const int t = lane & 3;
    const int wm = wid & 1;
    const int wn = wid >> 1;
    const int bm = blockIdx.y * CTAM;
    const int bn = blockIdx.x * CTAN;

    float c[4][8][4];
    #pragma unroll
    for (int i = 0; i < 4; i++)
        #pragma unroll
        for (int j = 0; j < 8; j++)
            #pragma unroll
            for (int q = 0; q < 4; q++) c[i][j][q] = 0.0f;

    auto load_chunk = [&](int stage, int kt) {
        const uint32_t sb = smem_u32 + (uint32_t)stage * STAGE_HALVES * 2;
        // A: 128 rows x 8 granules (16B) = 1024
        #pragma unroll
        for (int i = 0; i < 4; i++) {
            int gr = tid + i * 256;
            int row = gr >> 3, c8 = gr & 7;
            cp16(sb + (uint32_t)(row * (STRH * 2) + c8 * 16),
                 A + (size_t)(bm + row) * KDIM + kt + c8 * 8);
        }
        // W: 256 rows x 8 granules = 2048
        #pragma unroll
        for (int i = 0; i < 8; i++) {
            int gr = tid + i * 256;
            int row = gr >> 3, c8 = gr & 7;
            cp16(sb + (uint32_t)(A_HALVES * 2 + row * (STRH * 2) + c8 * 16),
                 W + (size_t)(bn + row) * KDIM + kt + c8 * 8);
        }
        CP_COMMIT();
    };

    load_chunk(0, 0);

    for (int ch = 0; ch < CHUNKS; ch++) {
        if (ch + 1 < CHUNKS) {
            load_chunk((ch + 1) & 1, (ch + 1) * BK);
            asm volatile("cp.async.wait_group 1;" ::: "memory");
        } else {
            asm volatile("cp.async.wait_group 0;" ::: "memory");
        }
        __syncthreads();

        const uint32_t* As = (const uint32_t*)(smem + (size_t)(ch & 1) * STAGE_HALVES);
        const uint32_t* Bs = As + A_HALVES / 2;

        #pragma unroll
        for (int s = 0; s < 4; s++) {           // k-steps of 16
            const int kw = s * 8 + t;           // 32-bit word col within row
            uint32_t a[4][4];
            #pragma unroll
            for (int mf = 0; mf < 4; mf++) {
                const int r0 = wm * 64 + mf * 16 + g;
                const uint32_t* p0 = As + r0 * (STRH / 2) + kw;
                const uint32_t* p1 = As + (r0 + 8) * (STRH / 2) + kw;
                a[mf][0] = p0[0];
                a[mf][1] = p1[0];
                a[mf][2] = p0[4];
                a[mf][3] = p1[4];
            }
            uint32_t b[8][2];
            #pragma unroll
            for (int nf = 0; nf < 8; nf++) {
                const int n0 = wn * 64 + nf * 8 + g;
                const uint32_t* p = Bs + n0 * (STRH / 2) + kw;
                b[nf][0] = p[0];
                b[nf][1] = p[4];
            }
            #pragma unroll
            for (int mf = 0; mf < 4; mf++)
                #pragma unroll
                for (int nf = 0; nf < 8; nf++)
                    mma_fp16(c[mf][nf][0], c[mf][nf][1], c[mf][nf][2], c[mf][nf][3],
                             a[mf][0], a[mf][1], a[mf][2], a[mf][3],
                             b[nf][0], b[nf][1]);
        }
        __syncthreads();
    }

    // ---- epilogue ----
    const float* b0 = gb.b0[z];
    const float* b1 = gb.b1[z];
    const float* b2 = gb.b2[z];
    const int accum = gb.accum;
    #pragma unroll
    for (int nf = 0; nf < 8; nf++) {
        const int col = bn + wn * 64 + nf * 8 + 2 * t;
        float bs0 = 0.0f, bs1 = 0.0f;
        if (!accum) {
            if (b0) { bs0 += b0[col]; bs1 += b0[col + 1]; }
            if (b1) { bs0 += b1[col]; bs1 += b1[col + 1]; }
            if (b2) { bs0 += b2[col]; bs1 += b2[col + 1]; }
        }
        #pragma unroll
        for (int mf = 0; mf < 4; mf++) {
            const int r = bm + wm * 64 + mf * 16 + g;
            float2 v0 = make_float2(c[mf][nf][0] + bs0, c[mf][nf][1] + bs1);
            float2 v1 = make_float2(c[mf][nf][2] + bs0, c[mf][nf][3] + bs1);
            float2* p0 = (float2*)(C + (size_t)r * DDIM + col);
            float2* p1 = (float2*)(C + (size_t)(r + 8) * DDIM + col);
            if (accum) {
                float2 o0 = *p0, o1 = *p1;
                v0.x += o0.x; v0.y += o0.y; v1.x += o1.x; v1.y += o1.y;
            }
            *p0 = v0;
            *p1 = v1;
        }
    }
}

// ---------------- elementwise ----------------
__global__ void rgmem_kernel(const float* __restrict__ mem0) {
    if (g_flags[0] == 0) return;
    const int total = BDIM * DDIM;
    for (int i = blockIdx.x * blockDim.x + threadIdx.x; i < total; i += gridDim.x * blockDim.x)
        g_preC[i] = sigmoidf_(g_preC[i]) * mem0[i];
}

__global__ void final_kernel(float* __restrict__ out, const float* __restrict__ b_dec) {
    const bool usemem = (g_flags[0] != 0);
    const int total = BDIM * DDIM;
    for (int i = blockIdx.x * blockDim.x + threadIdx.x; i < total; i += gridDim.x * blockDim.x) {
        float d = usemem ? g_dec[i] : b_dec[i & (DDIM - 1)];
        out[i] = d + sigmoidf_(g_preA[i]) * sigmoidf_(g_preB[i]);
    }
}

// ---------------- host orchestration ----------------
extern "C" void kernel_launch(void* const* d_in, const int* in_sizes, int n_in,
                              void* d_out, int out_size) {
    const float* x              = (const float*)d_in[0];
    const float* out0           = (const float*)d_in[1];
    const float* mem0           = (const float*)d_in[2];
    const float* w_inpgate      = (const float*)d_in[3];
    const float* b_inpgate      = (const float*)d_in[4];
    const float* w_rec_inpgate  = (const float*)d_in[5];
    const float* b_rec_inpgate  = (const float*)d_in[6];
    const float* w_mem_inpgate  = (const float*)d_in[7];
    const float* b_mem_inpgate  = (const float*)d_in[8];
    const float* w_inp          = (const float*)d_in[9];
    const float* b_inp          = (const float*)d_in[10];
    const float* w_rec_inp      = (const float*)d_in[11];
    const float* b_rec_inp      = (const float*)d_in[12];
    const float* w_readgate     = (const float*)d_in[13];
    const float* b_readgate     = (const float*)d_in[14];
    const float* w_rec_readgate = (const float*)d_in[15];
    const float* b_rec_readgate = (const float*)d_in[16];
    const float* w_mem_readgate = (const float*)d_in[17];
    const float* b_mem_readgate = (const float*)d_in[18];
    const float* w_decoder      = (const float*)d_in[19];
    const float* b_decoder      = (const float*)d_in[20];
    float* out = (float*)d_out;

    void *pA, *pB, *pC, *pD, *pax, *pay, *pw0, *pw1, *pw2;
    cudaGetSymbolAddress(&pA, g_preA); cudaGetSymbolAddress(&pB, g_preB);
    cudaGetSymbolAddress(&pC, g_preC); cudaGetSymbolAddress(&pD, g_dec);
    cudaGetSymbolAddress(&pax, g_ax);  cudaGetSymbolAddress(&pay, g_ay);
    cudaGetSymbolAddress(&pw0, g_w0);  cudaGetSymbolAddress(&pw1, g_w1);
    cudaGetSymbolAddress(&pw2, g_w2);
    float* preA = (float*)pA;  float* preB = (float*)pB;
    float* preC = (float*)pC;  float* dec  = (float*)pD;
    __half* ax = (__half*)pax; __half* ay = (__half*)pay;
    __half* w0h = (__half*)pw0; __half* w1h = (__half*)pw1; __half* w2h = (__half*)pw2;

    cudaFuncSetAttribute(gemm_fp16, cudaFuncAttributeMaxDynamicSharedMemorySize, GEMM_SMEM);

    const int nA4 = (BDIM * KDIM) / 4;
    const int nW4 = (DDIM * KDIM) / 4;

    // 1) flags
    reset_flags_kernel<<<1, 1>>>();
    scan_kernel<<<2048, 256>>>((const float4*)mem0, (const float4*)out0);

    // 2) convert x (always live)
    conv_kernel<<<1024, 256>>>((const float4*)x, (uint2*)ax, nA4, 0);

    // 3) convert live weights (w_readgate unconditionally — cheaper than a gated launch)
    {
        ConvBatch cb = {};
        cb.src[0] = (const float4*)w_inp;      cb.dst[0] = (uint2*)w0h; cb.flagsel[0] = 0;
        cb.src[1] = (const float4*)w_inpgate;  cb.dst[1] = (uint2*)w1h; cb.flagsel[1] = 0;
        cb.src[2] = (const float4*)w_readgate; cb.dst[2] = (uint2*)w2h; cb.flagsel[2] = 0;
        convw_batch_kernel<<<dim3(512, 1, 3), 256>>>(cb, nW4);
    }

    dim3 gg2(DDIM / CTAN, BDIM / CTAM, 2);
    dim3 gg3(DDIM / CTAN, BDIM / CTAM, 3);

    // 4) live GEMM batch: preA, preB (always), preC (mem0 gated)
    {
        GemmBatch gb = {};
        gb.W[0] = w0h; gb.C[0] = preA; gb.b0[0] = b_inp;      gb.b1[0] = b_rec_inp;      gb.b2[0] = nullptr;         gb.flagsel[0] = 0;
        gb.W[1] = w1h; gb.C[1] = preB; gb.b0[1] = b_inpgate;  gb.b1[1] = b_mem_inpgate;  gb.b2[1] = b_rec_inpgate;   gb.flagsel[1] = 0;
        gb.W[2] = w2h; gb.C[2] = preC; gb.b0[2] = b_readgate; gb.b1[2] = b_mem_readgate; gb.b2[2] = b_rec_readgate;  gb.flagsel[2] = 1;
        gb.accum = 0;
        gemm_fp16<<<gg3, 256, GEMM_SMEM>>>(ax, gb);
    }

    // 5) out0 recurrent terms  [out0 != 0]
    conv_kernel<<<1024, 256>>>((const float4*)out0, (uint2*)ay, nA4, 2);
    {
        ConvBatch cb = {};
        cb.src[0] = (const float4*)w_rec_inp;      cb.dst[0] = (uint2*)w0h; cb.flagsel[0] = 2;
        cb.src[1] = (const float4*)w_rec_inpgate;  cb.dst[1] = (uint2*)w1h; cb.flagsel[1] = 2;
        cb.src[2] = (const float4*)w_rec_readgate; cb.dst[2] = (uint2*)w2h; cb.flagsel[2] = 3;
        convw_batch_kernel<<<dim3(512, 1, 3), 256>>>(cb, nW4);
    }
    {
        GemmBatch gb = {};
        gb.W[0] = w0h; gb.C[0] = preA; gb.flagsel[0] = 2;
        gb.W[1] = w1h; gb.C[1] = preB; gb.flagsel[1] = 2;
        gb.W[2] = w2h; gb.C[2] = preC; gb.flagsel[2] = 3;
        gb.accum = 1;
        gemm_fp16<<<gg3, 256, GEMM_SMEM>>>(ay, gb);
    }

    // 6) mem0 terms  [mem0 != 0]
    conv_kernel<<<1024, 256>>>((const float4*)mem0, (uint2*)ay, nA4, 1);
    {
        ConvBatch cb = {};
        cb.src[0] = (const float4*)w_mem_inpgate;  cb.dst[0] = (uint2*)w0h; cb.flagsel[0] = 1;
        cb.src[1] = (const float4*)w_mem_readgate; cb.dst[1] = (uint2*)w1h; cb.flagsel[1] = 1;
        cb.src[2] = (const float4*)w_mem_readgate; cb.dst[2] = (uint2*)w1h; cb.flagsel[2] = 1; // unused z=2
        convw_batch_kernel<<<dim3(512, 1, 2), 256>>>(cb, nW4);
    }
    {
        GemmBatch gb = {};
        gb.W[0] = w0h; gb.C[0] = preB; gb.flagsel[0] = 1;
        gb.W[1] = w1h; gb.C[1] = preC; gb.flagsel[1] = 1;
        gb.accum = 1;
        gemm_fp16<<<gg2, 256, GEMM_SMEM>>>(ay, gb);
    }

    // 7) read_gate * mem0, decoder GEMM  [mem0 != 0]
    rgmem_kernel<<<4096, 256>>>(mem0);
    conv_kernel<<<1024, 256>>>((const float4*)preC, (uint2*)ay, nA4, 1);
    conv_kernel<<<512, 256>>>((const float4*)w_decoder, (uint2*)w0h, nW4, 1);
    {
        GemmBatch gb = {};
        gb.W[0] = w0h; gb.C[0] = dec; gb.b0[0] = b_decoder; gb.flagsel[0] = 1;
        gb.accum = 0;
        gemm_fp16<<<dim3(DDIM / CTAN, BDIM / CTAM, 1), 256, GEMM_SMEM>>>(ay, gb);
    }

    // 8) out = dec(or b_dec) + sig(preA)*sig(preB)
    final_kernel<<<4096, 256>>>(out, b_decoder);
}

// round 5
// speedup vs baseline: 5.3455x; 1.0639x over previous
#include <cuda_runtime.h>
#include <cuda_fp16.h>
#include <cstdint>
#include <math.h>

#define BDIM 4096
#define DDIM 2048
#define KDIM 2048

// ---------------- device scratch ----------------
__device__ int    g_flags[2];              // [0] mem0 nonzero, [1] out0 nonzero
__device__ float  g_preA[BDIM * DDIM];
__device__ float  g_preB[BDIM * DDIM];
__device__ float  g_preC[BDIM * DDIM];
__device__ float  g_dec [BDIM * DDIM];
__device__ __half g_ax  [BDIM * KDIM];
__device__ __half g_ay  [BDIM * KDIM];
__device__ __half g_w0  [DDIM * KDIM];
__device__ __half g_w1  [DDIM * KDIM];
__device__ __half g_w2  [DDIM * KDIM];

struct GemmBatch {
    const __half* W[3];
    float*        C[3];
    const float*  b0[3];
    const float*  b1[3];
    const float*  b2[3];
    int           flagsel[3];   // bit0: need mem0!=0, bit1: need out0!=0
    int           accum;
};

struct ConvBatch {
    const float4* src[4];
    uint2*        dst[4];
    int           n4[4];
    int           flagsel[4];
};

__device__ __forceinline__ float sigmoidf_(float v) { return 1.0f / (1.0f + expf(-v)); }

__device__ __forceinline__ uint32_t smem_to_u32(const void* p) {
    uint32_t a;
    asm("{ .reg .u64 t; cvta.to.shared.u64 t, %1; cvt.u32.u64 %0, t; }" : "=r"(a) : "l"(p));
    return a;
}

__device__ __forceinline__ void cp16(uint32_t dst, const void* src) {
    asm volatile("cp.async.cg.shared.global [%0], [%1], 16;" :: "r"(dst), "l"(src) : "memory");
}
#define CP_COMMIT() asm volatile("cp.async.commit_group;" ::: "memory")

__device__ __forceinline__ void ldm_x4(uint32_t& r0, uint32_t& r1, uint32_t& r2, uint32_t& r3,
                                       uint32_t addr) {
    asm volatile("ldmatrix.sync.aligned.m8n8.x4.shared.b16 {%0,%1,%2,%3}, [%4];"
                 : "=r"(r0), "=r"(r1), "=r"(r2), "=r"(r3) : "r"(addr));
}

__device__ __forceinline__ void mma_fp16(float* c,
                                         const uint32_t* a, const uint32_t* b) {
    asm volatile("mma.sync.aligned.m16n8k16.row.col.f32.f16.f16.f32 "
                 "{%0,%1,%2,%3}, {%4,%5,%6,%7}, {%8,%9}, {%0,%1,%2,%3};"
                 : "+f"(c[0]), "+f"(c[1]), "+f"(c[2]), "+f"(c[3])
                 : "r"(a[0]), "r"(a[1]), "r"(a[2]), "r"(a[3]), "r"(b[0]), "r"(b[1]));
}

__device__ __forceinline__ bool flag_ok(int flagsel) {
    if ((flagsel & 1) && g_flags[0] == 0) return false;
    if ((flagsel & 2) && g_flags[1] == 0) return false;
    return true;
}

// ---------------- flags ----------------
__global__ void reset_flags_kernel() { g_flags[0] = 0; g_flags[1] = 0; }

// fused: convert x -> fp16 AND scan mem0/out0 for nonzeros
__global__ void scanconv_kernel(const float4* __restrict__ x, uint2* __restrict__ ax,
                                const float4* __restrict__ m4, const float4* __restrict__ o4) {
    const int n4 = (BDIM * KDIM) / 4;
    for (int i = blockIdx.x * blockDim.x + threadIdx.x; i < n4; i += gridDim.x * blockDim.x) {
        float4 v = x[i];
        __half2 h0 = __floats2half2_rn(v.x, v.y);
        __half2 h1 = __floats2half2_rn(v.z, v.w);
        uint2 o;
        o.x = *(uint32_t*)&h0;
        o.y = *(uint32_t*)&h1;
        ax[i] = o;
    }
    const int total = (BDIM * DDIM) / 4;
    bool nzm = false, nzo = false;
    for (int i = blockIdx.x * blockDim.x + threadIdx.x; i < total; i += gridDim.x * blockDim.x) {
        float4 v = m4[i];
        nzm |= (v.x != 0.0f) | (v.y != 0.0f) | (v.z != 0.0f) | (v.w != 0.0f);
        float4 u = o4[i];
        nzo |= (u.x != 0.0f) | (u.y != 0.0f) | (u.z != 0.0f) | (u.w != 0.0f);
    }
    if (nzm) atomicOr(&g_flags[0], 1);
    if (nzo) atomicOr(&g_flags[1], 1);
}

// ---------------- batched fp32 -> fp16 conversion ----------------
__global__ void conv_batch_kernel(ConvBatch cb) {
    const int z = blockIdx.z;
    if (!flag_ok(cb.flagsel[z])) return;
    const float4* __restrict__ src = cb.src[z];
    uint2* __restrict__ dst = cb.dst[z];
    const int n4 = cb.n4[z];
    for (int i = blockIdx.x * blockDim.x + threadIdx.x; i < n4; i += gridDim.x * blockDim.x) {
        float4 v = src[i];
        __half2 h0 = __floats2half2_rn(v.x, v.y);
        __half2 h1 = __floats2half2_rn(v.z, v.w);
        uint2 o;
        o.x = *(uint32_t*)&h0;
        o.y = *(uint32_t*)&h1;
        dst[i] = o;
    }
}

// ---------------- fp16 mma.sync GEMM ----------------
// CTA tile 128(M) x 256(N) x 64(K); 16 warps = 2(M) x 8(N), warp tile 64x32, ldmatrix.
#define BK 64
#define CHUNKS (KDIM / BK)
#define CTAM 128
#define CTAN 256
#define STRH 72                             // halves per row (144B, pad keeps ldmatrix conflict-free)
#define A_BYTES (CTAM * STRH * 2)           // 18432
#define B_BYTES (CTAN * STRH * 2)           // 36864
#define STAGE_BYTES (A_BYTES + B_BYTES)     // 55296
#define GEMM_SMEM (2 * STAGE_BYTES)         // 110592

__global__ __launch_bounds__(512, 1)
void gemm_fp16(const __half* __restrict__ A, GemmBatch gb, int epi_mode,
               const float* __restrict__ preA_in, float* __restrict__ outp,
               const float* __restrict__ bdec)
{
    const int z = blockIdx.z;
    if (!flag_ok(gb.flagsel[z])) return;
    const __half* __restrict__ W = gb.W[z];
    float* __restrict__ C = gb.C[z];

    extern __shared__ char smem[];
    const uint32_t sb0 = smem_to_u32(smem);

    const int tid = threadIdx.x;
    const int wid = tid >> 5;
    const int lane = tid & 31;
    const int g = lane >> 2;
    const int t = lane & 3;
    const int wm = wid & 1;       // 0..1
    const int wn = wid >> 1;      // 0..7
    const int bm = blockIdx.y * CTAM;
    const int bn = blockIdx.x * CTAN;

    float c[4][4][4];
    #pragma unroll
    for (int i = 0; i < 4; i++)
        #pragma unroll
        for (int j = 0; j < 4; j++)
            #pragma unroll
            for (int q = 0; q < 4; q++) c[i][j][q] = 0.0f;

    // ldmatrix per-lane addressing
    const uint32_t a_row = (uint32_t)(wm * 64 + (lane & 15));
    const uint32_t a_kb  = (uint32_t)((lane >> 4) * 16);              // bytes: 0 or 16
    const uint32_t b_row = (uint32_t)(wn * 32 + (lane & 7) + ((lane & 16) ? 8 : 0));
    const uint32_t b_kb  = (uint32_t)((lane & 8) ? 16 : 0);           // bytes

    auto load_chunk = [&](int stage, int kt) {
        const uint32_t sb = sb0 + (uint32_t)stage * STAGE_BYTES;
        // A: 1024 granules of 16B
        #pragma unroll
        for (int i = 0; i < 2; i++) {
            int gr = tid + i * 512;
            int row = gr >> 3, c8 = gr & 7;
            cp16(sb + (uint32_t)(row * 144 + c8 * 16),
                 A + (size_t)(bm + row) * KDIM + kt + c8 * 8);
        }
        // W: 2048 granules
        #pragma unroll
        for (int i = 0; i < 4; i++) {
            int gr = tid + i * 512;
            int row = gr >> 3, c8 = gr & 7;
            cp16(sb + (uint32_t)(A_BYTES + row * 144 + c8 * 16),
                 W + (size_t)(bn + row) * KDIM + kt + c8 * 8);
        }
        CP_COMMIT();
    };

    load_chunk(0, 0);

    for (int ch = 0; ch < CHUNKS; ch++) {
        if (ch + 1 < CHUNKS) {
            load_chunk((ch + 1) & 1, (ch + 1) * BK);
            asm volatile("cp.async.wait_group 1;" ::: "memory");
        } else {
            asm volatile("cp.async.wait_group 0;" ::: "memory");
        }
        __syncthreads();

        const uint32_t As = sb0 + (uint32_t)(ch & 1) * STAGE_BYTES;
        const uint32_t Bs = As + A_BYTES;

        #pragma unroll
        for (int s = 0; s < 4; s++) {
            const uint32_t kb = (uint32_t)(s * 32);     // 16 halves per step
            uint32_t a[4][4];
            #pragma unroll
            for (int mf = 0; mf < 4; mf++)
                ldm_x4(a[mf][0], a[mf][1], a[mf][2], a[mf][3],
                       As + (a_row + mf * 16) * 144 + kb + a_kb);
            uint32_t b[4][2];
            #pragma unroll
            for (int nh = 0; nh < 2; nh++) {
                uint32_t r0, r1, r2, r3;
                ldm_x4(r0, r1, r2, r3, Bs + (b_row + nh * 16) * 144 + kb + b_kb);
                b[2 * nh][0] = r0;  b[2 * nh][1] = r1;
                b[2 * nh + 1][0] = r2;  b[2 * nh + 1][1] = r3;
            }
            #pragma unroll
            for (int mf = 0; mf < 4; mf++)
                #pragma unroll
                for (int nf = 0; nf < 4; nf++)
                    mma_fp16(c[mf][nf], a[mf], b[nf]);
        }
        __syncthreads();
    }

    // ---- epilogue ----
    const float* b0 = gb.b0[z];
    const float* b1 = gb.b1[z];
    const float* b2 = gb.b2[z];
    const int accum = gb.accum;

    if (epi_mode == 0) {
        #pragma unroll
        for (int nf = 0; nf < 4; nf++) {
            const int col = bn + wn * 32 + nf * 8 + 2 * t;
            float bs0 = 0.0f, bs1 = 0.0f;
            if (!accum) {
                if (b0) { bs0 += b0[col]; bs1 += b0[col + 1]; }
                if (b1) { bs0 += b1[col]; bs1 += b1[col + 1]; }
                if (b2) { bs0 += b2[col]; bs1 += b2[col + 1]; }
            }
            #pragma unroll
            for (int mf = 0; mf < 4; mf++) {
                const int r = bm + wm * 64 + mf * 16 + g;
                float2 v0 = make_float2(c[mf][nf][0] + bs0, c[mf][nf][1] + bs1);
                float2 v1 = make_float2(c[mf][nf][2] + bs0, c[mf][nf][3] + bs1);
                float2* p0 = (float2*)(C + (size_t)r * DDIM + col);
                float2* p1 = (float2*)(C + (size_t)(r + 8) * DDIM + col);
                if (accum) {
                    float2 o0 = *p0, o1 = *p1;
                    v0.x += o0.x; v0.y += o0.y; v1.x += o1.x; v1.y += o1.y;
                }
                *p0 = v0;
                *p1 = v1;
            }
        }
    } else {
        // fused final (preB GEMM): fast path writes out directly, slow path stores raw preB
        const bool slow = (g_flags[0] | g_flags[1]) != 0;
        #pragma unroll
        for (int nf = 0; nf < 4; nf++) {
            const int col = bn + wn * 32 + nf * 8 + 2 * t;
            float bs0 = b0[col] + b1[col] + b2[col];
            float bs1 = b0[col + 1] + b1[col + 1] + b2[col + 1];
            float d0 = bdec[col], d1 = bdec[col + 1];
            #pragma unroll
            for (int mf = 0; mf < 4; mf++) {
                const int r = bm + wm * 64 + mf * 16 + g;
                float2 v0 = make_float2(c[mf][nf][0] + bs0, c[mf][nf][1] + bs1);
                float2 v1 = make_float2(c[mf][nf][2] + bs0, c[mf][nf][3] + bs1);
                if (slow) {
                    *(float2*)(C + (size_t)r * DDIM + col) = v0;
                    *(float2*)(C + (size_t)(r + 8) * DDIM + col) = v1;
                } else {
                    float2 pa0 = *(const float2*)(preA_in + (size_t)r * DDIM + col);
                    float2 pa1 = *(const float2*)(preA_in + (size_t)(r + 8) * DDIM + col);
                    float2 o0, o1;
                    o0.x = d0 + sigmoidf_(pa0.x) * sigmoidf_(v0.x);
                    o0.y = d1 + sigmoidf_(pa0.y) * sigmoidf_(v0.y);
                    o1.x = d0 + sigmoidf_(pa1.x) * sigmoidf_(v1.x);
                    o1.y = d1 + sigmoidf_(pa1.y) * sigmoidf_(v1.y);
                    *(float2*)(outp + (size_t)r * DDIM + col) = o0;
                    *(float2*)(outp + (size_t)(r + 8) * DDIM + col) = o1;
                }
            }
        }
    }
}

// ---------------- gated elementwise ----------------
// ay = fp16( sigmoid(preC) * mem0 )   [mem0 != 0]
__global__ void rgconv_kernel(const float4* __restrict__ mem0, uint2* __restrict__ ay) {
    if (g_flags[0] == 0) return;
    const int n4 = (BDIM * DDIM) / 4;
    const float4* __restrict__ pc = (const float4*)g_preC;
    for (int i = blockIdx.x * blockDim.x + threadIdx.x; i < n4; i += gridDim.x * blockDim.x) {
        float4 p = pc[i];
        float4 m = mem0[i];
        __half2 h0 = __floats2half2_rn(sigmoidf_(p.x) * m.x, sigmoidf_(p.y) * m.y);
        __half2 h1 = __floats2half2_rn(sigmoidf_(p.z) * m.z, sigmoidf_(p.w) * m.w);
        uint2 o;
        o.x = *(uint32_t*)&h0;
        o.y = *(uint32_t*)&h1;
        ay[i] = o;
    }
}

// slow-path final (only when mem0!=0 or out0!=0)
__global__ void final_kernel(float* __restrict__ out, const float* __restrict__ b_dec) {
    if (g_flags[0] == 0 && g_flags[1] == 0) return;
    const bool usemem = (g_flags[0] != 0);
    const int total = BDIM * DDIM;
    for (int i = blockIdx.x * blockDim.x + threadIdx.x; i < total; i += gridDim.x * blockDim.x) {
        float d = usemem ? g_dec[i] : b_dec[i & (DDIM - 1)];
        out[i] = d + sigmoidf_(g_preA[i]) * sigmoidf_(g_preB[i]);
    }
}

// ---------------- host orchestration ----------------
extern "C" void kernel_launch(void* const* d_in, const int* in_sizes, int n_in,
                              void* d_out, int out_size) {
    const float* x              = (const float*)d_in[0];
    const float* out0           = (const float*)d_in[1];
    const float* mem0           = (const float*)d_in[2];
    const float* w_inpgate      = (const float*)d_in[3];
    const float* b_inpgate      = (const float*)d_in[4];
    const float* w_rec_inpgate  = (const float*)d_in[5];
    const float* b_rec_inpgate  = (const float*)d_in[6];
    const float* w_mem_inpgate  = (const float*)d_in[7];
    const float* b_mem_inpgate  = (const float*)d_in[8];
    const float* w_inp          = (const float*)d_in[9];
    const float* b_inp          = (const float*)d_in[10];
    const float* w_rec_inp      = (const float*)d_in[11];
    const float* b_rec_inp      = (const float*)d_in[12];
    const float* w_readgate     = (const float*)d_in[13];
    const float* b_readgate     = (const float*)d_in[14];
    const float* w_rec_readgate = (const float*)d_in[15];
    const float* b_rec_readgate = (const float*)d_in[16];
    const float* w_mem_readgate = (const float*)d_in[17];
    const float* b_mem_readgate = (const float*)d_in[18];
    const float* w_decoder      = (const float*)d_in[19];
    const float* b_decoder      = (const float*)d_in[20];
    float* out = (float*)d_out;

    void *pA, *pB, *pC, *pD, *pax, *pay, *pw0, *pw1, *pw2;
    cudaGetSymbolAddress(&pA, g_preA); cudaGetSymbolAddress(&pB, g_preB);
    cudaGetSymbolAddress(&pC, g_preC); cudaGetSymbolAddress(&pD, g_dec);
    cudaGetSymbolAddress(&pax, g_ax);  cudaGetSymbolAddress(&pay, g_ay);
    cudaGetSymbolAddress(&pw0, g_w0);  cudaGetSymbolAddress(&pw1, g_w1);
    cudaGetSymbolAddress(&pw2, g_w2);
    float* preA = (float*)pA;  float* preB = (float*)pB;
    float* preC = (float*)pC;  float* dec  = (float*)pD;
    __half* ax = (__half*)pax; __half* ay = (__half*)pay;
    __half* w0h = (__half*)pw0; __half* w1h = (__half*)pw1; __half* w2h = (__half*)pw2;

    cudaFuncSetAttribute(gemm_fp16, cudaFuncAttributeMaxDynamicSharedMemorySize, GEMM_SMEM);

    const int nA4 = (BDIM * KDIM) / 4;
    const int nW4 = (DDIM * KDIM) / 4;

    // 1) flags + convert x (fused)
    reset_flags_kernel<<<1, 1>>>();
    scanconv_kernel<<<2048, 256>>>((const float4*)x, (uint2*)ax,
                                   (const float4*)mem0, (const float4*)out0);

    // 2) convert the three x-side weights (ungated)
    {
        ConvBatch cb = {};
        cb.src[0] = (const float4*)w_inp;      cb.dst[0] = (uint2*)w0h; cb.n4[0] = nW4; cb.flagsel[0] = 0;
        cb.src[1] = (const float4*)w_inpgate;  cb.dst[1] = (uint2*)w1h; cb.n4[1] = nW4; cb.flagsel[1] = 0;
        cb.src[2] = (const float4*)w_readgate; cb.dst[2] = (uint2*)w2h; cb.n4[2] = nW4; cb.flagsel[2] = 0;
        conv_batch_kernel<<<dim3(512, 1, 3), 256>>>(cb);
    }

    // 3) GEMM batch: preA (always), preC (mem gated)
    {
        GemmBatch gb = {};
        gb.W[0] = w0h; gb.C[0] = preA; gb.b0[0] = b_inp;      gb.b1[0] = b_rec_inp;      gb.flagsel[0] = 0;
        gb.W[1] = w2h; gb.C[1] = preC; gb.b0[1] = b_readgate; gb.b1[1] = b_mem_readgate; gb.b2[1] = b_rec_readgate; gb.flagsel[1] = 1;
        gb.accum = 0;
        gemm_fp16<<<dim3(8, 32, 2), 512, GEMM_SMEM>>>(ax, gb, 0, nullptr, nullptr, nullptr);
    }

    // 4) preB GEMM with fused final epilogue (fast path writes `out` directly)
    {
        GemmBatch gb = {};
        gb.W[0] = w1h; gb.C[0] = preB;
        gb.b0[0] = b_inpgate; gb.b1[0] = b_mem_inpgate; gb.b2[0] = b_rec_inpgate;
        gb.flagsel[0] = 0; gb.accum = 0;
        gemm_fp16<<<dim3(8, 32, 1), 512, GEMM_SMEM>>>(ax, gb, 1, preA, out, b_decoder);
    }

    // 5) out0 recurrent terms  [out0 != 0]
    {
        ConvBatch cb = {};
        cb.src[0] = (const float4*)out0;            cb.dst[0] = (uint2*)ay;  cb.n4[0] = nA4; cb.flagsel[0] = 2;
        cb.src[1] = (const float4*)w_rec_inp;       cb.dst[1] = (uint2*)w0h; cb.n4[1] = nW4; cb.flagsel[1] = 2;
        cb.src[2] = (const float4*)w_rec_inpgate;   cb.dst[2] = (uint2*)w1h; cb.n4[2] = nW4; cb.flagsel[2] = 2;
        cb.src[3] = (const float4*)w_rec_readgate;  cb.dst[3] = (uint2*)w2h; cb.n4[3] = nW4; cb.flagsel[3] = 3;
        conv_batch_kernel<<<dim3(512, 1, 4), 256>>>(cb);
    }
    {
        GemmBatch gb = {};
        gb.W[0] = w0h; gb.C[0] = preA; gb.flagsel[0] = 2;
        gb.W[1] = w1h; gb.C[1] = preB; gb.flagsel[1] = 2;
        gb.W[2] = w2h; gb.C[2] = preC; gb.flagsel[2] = 3;
        gb.accum = 1;
        gemm_fp16<<<dim3(8, 32, 3), 512, GEMM_SMEM>>>(ay, gb, 0, nullptr, nullptr, nullptr);
    }

    // 6) mem0 terms  [mem0 != 0]
    {
        ConvBatch cb = {};
        cb.src[0] = (const float4*)mem0;            cb.dst[0] = (uint2*)ay;  cb.n4[0] = nA4; cb.flagsel[0] = 1;
        cb.src[1] = (const float4*)w_mem_inpgate;   cb.dst[1] = (uint2*)w0h; cb.n4[1] = nW4; cb.flagsel[1] = 1;
        cb.src[2] = (const float4*)w_mem_readgate;  cb.dst[2] = (uint2*)w1h; cb.n4[2] = nW4; cb.flagsel[2] = 1;
        conv_batch_kernel<<<dim3(512, 1, 3), 256>>>(cb);
    }
    {
        GemmBatch gb = {};
        gb.W[0] = w0h; gb.C[0] = preB; gb.flagsel[0] = 1;
        gb.W[1] = w1h; gb.C[1] = preC; gb.flagsel[1] = 1;
        gb.accum = 1;
        gemm_fp16<<<dim3(8, 32, 2), 512, GEMM_SMEM>>>(ay, gb, 0, nullptr, nullptr, nullptr);
    }

    // 7) ay = fp16(sigmoid(preC)*mem0), convert w_decoder, decoder GEMM  [mem0 != 0]
    rgconv_kernel<<<2048, 256>>>((const float4*)mem0, (uint2*)ay);
    {
        ConvBatch cb = {};
        cb.src[0] = (const float4*)w_decoder; cb.dst[0] = (uint2*)w0h; cb.n4[0] = nW4; cb.flagsel[0] = 1;
        conv_batch_kernel<<<dim3(512, 1, 1), 256>>>(cb);
    }
    {
        GemmBatch gb = {};
        gb.W[0] = w0h; gb.C[0] = dec; gb.b0[0] = b_decoder; gb.flagsel[0] = 1;
        gb.accum = 0;
        gemm_fp16<<<dim3(8, 32, 1), 512, GEMM_SMEM>>>(ay, gb, 0, nullptr, nullptr, nullptr);
    }

    // 8) slow-path final (gated off when both states are zero)
    final_kernel<<<2048, 256>>>(out, b_decoder);
}

// round 6
// speedup vs baseline: 5.4380x; 1.0173x over previous
#include <cuda_runtime.h>
#include <cuda_fp16.h>
#include <cstdint>
#include <math.h>

#define BDIM 4096
#define DDIM 2048
#define KDIM 2048

// ---------------- device scratch ----------------
__device__ int    g_flags[2];              // [0] mem0 nonzero, [1] out0 nonzero
__device__ float  g_preA[BDIM * DDIM];
__device__ float  g_preB[BDIM * DDIM];
__device__ float  g_preC[BDIM * DDIM];
__device__ float  g_dec [BDIM * DDIM];
__device__ __half g_ax  [BDIM * KDIM];
__device__ __half g_ay  [BDIM * KDIM];
__device__ __half g_w0  [DDIM * KDIM];
__device__ __half g_w1  [DDIM * KDIM];
__device__ __half g_w2  [DDIM * KDIM];

struct GemmBatch {
    const __half* W[3];
    float*        C[3];
    const float*  b0[3];
    const float*  b1[3];
    const float*  b2[3];
    int           flagsel[3];   // bit0: need mem0!=0, bit1: need out0!=0
    int           accum;
};

struct ConvBatch {
    const float4* src[4];
    uint2*        dst[4];
    int           n4[4];
    int           flagsel[4];
};

__device__ __forceinline__ float sigmoidf_(float v) { return 1.0f / (1.0f + expf(-v)); }

__device__ __forceinline__ uint32_t smem_to_u32(const void* p) {
    uint32_t a;
    asm("{ .reg .u64 t; cvta.to.shared.u64 t, %1; cvt.u32.u64 %0, t; }" : "=r"(a) : "l"(p));
    return a;
}

__device__ __forceinline__ void cp16(uint32_t dst, const void* src) {
    asm volatile("cp.async.cg.shared.global [%0], [%1], 16;" :: "r"(dst), "l"(src) : "memory");
}
#define CP_COMMIT() asm volatile("cp.async.commit_group;" ::: "memory")

__device__ __forceinline__ void ldm_x4(uint32_t& r0, uint32_t& r1, uint32_t& r2, uint32_t& r3,
                                       uint32_t addr) {
    asm volatile("ldmatrix.sync.aligned.m8n8.x4.shared.b16 {%0,%1,%2,%3}, [%4];"
                 : "=r"(r0), "=r"(r1), "=r"(r2), "=r"(r3) : "r"(addr));
}

__device__ __forceinline__ void mma_fp16(float* c,
                                         const uint32_t* a, const uint32_t* b) {
    asm volatile("mma.sync.aligned.m16n8k16.row.col.f32.f16.f16.f32 "
                 "{%0,%1,%2,%3}, {%4,%5,%6,%7}, {%8,%9}, {%0,%1,%2,%3};"
                 : "+f"(c[0]), "+f"(c[1]), "+f"(c[2]), "+f"(c[3])
                 : "r"(a[0]), "r"(a[1]), "r"(a[2]), "r"(a[3]), "r"(b[0]), "r"(b[1]));
}

__device__ __forceinline__ bool flag_ok(int flagsel) {
    if ((flagsel & 1) && g_flags[0] == 0) return false;
    if ((flagsel & 2) && g_flags[1] == 0) return false;
    return true;
}

// ---------------- flags ----------------
__global__ void reset_flags_kernel() { g_flags[0] = 0; g_flags[1] = 0; }

// fused: convert x -> fp16 AND scan mem0/out0 for nonzeros
__global__ void scanconv_kernel(const float4* __restrict__ x, uint2* __restrict__ ax,
                                const float4* __restrict__ m4, const float4* __restrict__ o4) {
    const int n4 = (BDIM * KDIM) / 4;
    for (int i = blockIdx.x * blockDim.x + threadIdx.x; i < n4; i += gridDim.x * blockDim.x) {
        float4 v = x[i];
        __half2 h0 = __floats2half2_rn(v.x, v.y);
        __half2 h1 = __floats2half2_rn(v.z, v.w);
        uint2 o;
        o.x = *(uint32_t*)&h0;
        o.y = *(uint32_t*)&h1;
        ax[i] = o;
    }
    const int total = (BDIM * DDIM) / 4;
    bool nzm = false, nzo = false;
    for (int i = blockIdx.x * blockDim.x + threadIdx.x; i < total; i += gridDim.x * blockDim.x) {
        float4 v = m4[i];
        nzm |= (v.x != 0.0f) | (v.y != 0.0f) | (v.z != 0.0f) | (v.w != 0.0f);
        float4 u = o4[i];
        nzo |= (u.x != 0.0f) | (u.y != 0.0f) | (u.z != 0.0f) | (u.w != 0.0f);
    }
    if (nzm) atomicOr(&g_flags[0], 1);
    if (nzo) atomicOr(&g_flags[1], 1);
}

// ---------------- batched fp32 -> fp16 conversion ----------------
__global__ void conv_batch_kernel(ConvBatch cb) {
    const int z = blockIdx.z;
    if (!flag_ok(cb.flagsel[z])) return;
    const float4* __restrict__ src = cb.src[z];
    uint2* __restrict__ dst = cb.dst[z];
    const int n4 = cb.n4[z];
    for (int i = blockIdx.x * blockDim.x + threadIdx.x; i < n4; i += gridDim.x * blockDim.x) {
        float4 v = src[i];
        __half2 h0 = __floats2half2_rn(v.x, v.y);
        __half2 h1 = __floats2half2_rn(v.z, v.w);
        uint2 o;
        o.x = *(uint32_t*)&h0;
        o.y = *(uint32_t*)&h1;
        dst[i] = o;
    }
}

// ---------------- fp16 mma.sync GEMM ----------------
// CTA tile 128(M) x 128(N) x 64(K); 8 warps = 2(M) x 4(N), warp tile 64x32.
// 3-stage cp.async pipeline, 2 CTAs/SM.
#define BK 64
#define CHUNKS (KDIM / BK)
#define CTAM 128
#define CTAN 128
#define STRB 144                            // bytes per k-row (64 halves + 8 pad)
#define A_BYTES (CTAM * STRB)               // 18432
#define B_BYTES (CTAN * STRB)               // 18432
#define STAGE_BYTES (A_BYTES + B_BYTES)     // 36864
#define NSTAGE 3
#define GEMM_SMEM (NSTAGE * STAGE_BYTES)    // 110592

__global__ __launch_bounds__(256, 2)
void gemm_fp16(const __half* __restrict__ A, GemmBatch gb, int epi_mode,
               const float* __restrict__ preA_in, float* __restrict__ outp,
               const float* __restrict__ bdec)
{
    const int z = blockIdx.z;
    if (!flag_ok(gb.flagsel[z])) return;
    const __half* __restrict__ W = gb.W[z];
    float* __restrict__ C = gb.C[z];

    extern __shared__ char smem[];
    const uint32_t sb0 = smem_to_u32(smem);

    const int tid = threadIdx.x;
    const int wid = tid >> 5;
    const int lane = tid & 31;
    const int g = lane >> 2;
    const int t = lane & 3;
    const int wm = wid & 1;       // 0..1
    const int wn = wid >> 1;      // 0..3
    const int bm = blockIdx.y * CTAM;
    const int bn = blockIdx.x * CTAN;

    float c[4][4][4];
    #pragma unroll
    for (int i = 0; i < 4; i++)
        #pragma unroll
        for (int j = 0; j < 4; j++)
            #pragma unroll
            for (int q = 0; q < 4; q++) c[i][j][q] = 0.0f;

    // ldmatrix per-lane addressing
    const uint32_t a_row = (uint32_t)(wm * 64 + (lane & 15));
    const uint32_t a_kb  = (uint32_t)((lane >> 4) * 16);
    const uint32_t b_row = (uint32_t)(wn * 32 + (lane & 7) + ((lane & 16) ? 8 : 0));
    const uint32_t b_kb  = (uint32_t)((lane & 8) ? 16 : 0);

    auto load_chunk = [&](int stage, int kt) {
        const uint32_t sb = sb0 + (uint32_t)stage * STAGE_BYTES;
        // A: 128 rows x 8 granules = 1024
        #pragma unroll
        for (int i = 0; i < 4; i++) {
            int gr = tid + i * 256;
            int row = gr >> 3, c8 = gr & 7;
            cp16(sb + (uint32_t)(row * STRB + c8 * 16),
                 A + (size_t)(bm + row) * KDIM + kt + c8 * 8);
        }
        // W: 128 rows x 8 granules = 1024
        #pragma unroll
        for (int i = 0; i < 4; i++) {
            int gr = tid + i * 256;
            int row = gr >> 3, c8 = gr & 7;
            cp16(sb + (uint32_t)(A_BYTES + row * STRB + c8 * 16),
                 W + (size_t)(bn + row) * KDIM + kt + c8 * 8);
        }
        CP_COMMIT();
    };

    load_chunk(0, 0);
    load_chunk(1, BK);

    int stage = 0;
    for (int ch = 0; ch < CHUNKS; ch++) {
        if (ch + 2 < CHUNKS) {
            int ns = stage + 2; if (ns >= NSTAGE) ns -= NSTAGE;
            load_chunk(ns, (ch + 2) * BK);
            asm volatile("cp.async.wait_group 2;" ::: "memory");
        } else if (ch + 1 < CHUNKS) {
            asm volatile("cp.async.wait_group 1;" ::: "memory");
        } else {
            asm volatile("cp.async.wait_group 0;" ::: "memory");
        }
        __syncthreads();

        const uint32_t As = sb0 + (uint32_t)stage * STAGE_BYTES;
        const uint32_t Bs = As + A_BYTES;

        #pragma unroll
        for (int s = 0; s < 4; s++) {
            const uint32_t kb = (uint32_t)(s * 32);
            uint32_t a[4][4];
            #pragma unroll
            for (int mf = 0; mf < 4; mf++)
                ldm_x4(a[mf][0], a[mf][1], a[mf][2], a[mf][3],
                       As + (a_row + mf * 16) * STRB + kb + a_kb);
            uint32_t b[4][2];
            #pragma unroll
            for (int nh = 0; nh < 2; nh++) {
                uint32_t r0, r1, r2, r3;
                ldm_x4(r0, r1, r2, r3, Bs + (b_row + nh * 16) * STRB + kb + b_kb);
                b[2 * nh][0] = r0;      b[2 * nh][1] = r1;
                b[2 * nh + 1][0] = r2;  b[2 * nh + 1][1] = r3;
            }
            #pragma unroll
            for (int mf = 0; mf < 4; mf++)
                #pragma unroll
                for (int nf = 0; nf < 4; nf++)
                    mma_fp16(c[mf][nf], a[mf], b[nf]);
        }
        __syncthreads();
        if (++stage >= NSTAGE) stage = 0;
    }

    // ---- epilogue ----
    const float* b0 = gb.b0[z];
    const float* b1 = gb.b1[z];
    const float* b2 = gb.b2[z];
    const int accum = gb.accum;

    if (epi_mode == 0) {
        #pragma unroll
        for (int nf = 0; nf < 4; nf++) {
            const int col = bn + wn * 32 + nf * 8 + 2 * t;
            float bs0 = 0.0f, bs1 = 0.0f;
            if (!accum) {
                if (b0) { bs0 += b0[col]; bs1 += b0[col + 1]; }
                if (b1) { bs0 += b1[col]; bs1 += b1[col + 1]; }
                if (b2) { bs0 += b2[col]; bs1 += b2[col + 1]; }
            }
            #pragma unroll
            for (int mf = 0; mf < 4; mf++) {
                const int r = bm + wm * 64 + mf * 16 + g;
                float2 v0 = make_float2(c[mf][nf][0] + bs0, c[mf][nf][1] + bs1);
                float2 v1 = make_float2(c[mf][nf][2] + bs0, c[mf][nf][3] + bs1);
                float2* p0 = (float2*)(C + (size_t)r * DDIM + col);
                float2* p1 = (float2*)(C + (size_t)(r + 8) * DDIM + col);
                if (accum) {
                    float2 o0 = *p0, o1 = *p1;
                    v0.x += o0.x; v0.y += o0.y; v1.x += o1.x; v1.y += o1.y;
                }
                *p0 = v0;
                *p1 = v1;
            }
        }
    } else {
        // fused final (preB GEMM): fast path writes out directly, slow path stores raw preB
        const bool slow = (g_flags[0] | g_flags[1]) != 0;
        #pragma unroll
        for (int nf = 0; nf < 4; nf++) {
            const int col = bn + wn * 32 + nf * 8 + 2 * t;
            float bs0 = b0[col] + b1[col] + b2[col];
            float bs1 = b0[col + 1] + b1[col + 1] + b2[col + 1];
            float d0 = bdec[col], d1 = bdec[col + 1];
            #pragma unroll
            for (int mf = 0; mf < 4; mf++) {
                const int r = bm + wm * 64 + mf * 16 + g;
                float2 v0 = make_float2(c[mf][nf][0] + bs0, c[mf][nf][1] + bs1);
                float2 v1 = make_float2(c[mf][nf][2] + bs0, c[mf][nf][3] + bs1);
                if (slow) {
                    *(float2*)(C + (size_t)r * DDIM + col) = v0;
                    *(float2*)(C + (size_t)(r + 8) * DDIM + col) = v1;
                } else {
                    float2 pa0 = *(const float2*)(preA_in + (size_t)r * DDIM + col);
                    float2 pa1 = *(const float2*)(preA_in + (size_t)(r + 8) * DDIM + col);
                    float2 o0, o1;
                    o0.x = d0 + sigmoidf_(pa0.x) * sigmoidf_(v0.x);
                    o0.y = d1 + sigmoidf_(pa0.y) * sigmoidf_(v0.y);
                    o1.x = d0 + sigmoidf_(pa1.x) * sigmoidf_(v1.x);
                    o1.y = d1 + sigmoidf_(pa1.y) * sigmoidf_(v1.y);
                    *(float2*)(outp + (size_t)r * DDIM + col) = o0;
                    *(float2*)(outp + (size_t)(r + 8) * DDIM + col) = o1;
                }
            }
        }
    }
}

// ---------------- gated elementwise ----------------
__global__ void rgconv_kernel(const float4* __restrict__ mem0, uint2* __restrict__ ay) {
    if (g_flags[0] == 0) return;
    const int n4 = (BDIM * DDIM) / 4;
    const float4* __restrict__ pc = (const float4*)g_preC;
    for (int i = blockIdx.x * blockDim.x + threadIdx.x; i < n4; i += gridDim.x * blockDim.x) {
        float4 p = pc[i];
        float4 m = mem0[i];
        __half2 h0 = __floats2half2_rn(sigmoidf_(p.x) * m.x, sigmoidf_(p.y) * m.y);
        __half2 h1 = __floats2half2_rn(sigmoidf_(p.z) * m.z, sigmoidf_(p.w) * m.w);
        uint2 o;
        o.x = *(uint32_t*)&h0;
        o.y = *(uint32_t*)&h1;
        ay[i] = o;
    }
}

__global__ void final_kernel(float* __restrict__ out, const float* __restrict__ b_dec) {
    if (g_flags[0] == 0 && g_flags[1] == 0) return;
    const bool usemem = (g_flags[0] != 0);
    const int total = BDIM * DDIM;
    for (int i = blockIdx.x * blockDim.x + threadIdx.x; i < total; i += gridDim.x * blockDim.x) {
        float d = usemem ? g_dec[i] : b_dec[i & (DDIM - 1)];
        out[i] = d + sigmoidf_(g_preA[i]) * sigmoidf_(g_preB[i]);
    }
}

// ---------------- host orchestration ----------------
extern "C" void kernel_launch(void* const* d_in, const int* in_sizes, int n_in,
                              void* d_out, int out_size) {
    const float* x              = (const float*)d_in[0];
    const float* out0           = (const float*)d_in[1];
    const float* mem0           = (const float*)d_in[2];
    const float* w_inpgate      = (const float*)d_in[3];
    const float* b_inpgate      = (const float*)d_in[4];
    const float* w_rec_inpgate  = (const float*)d_in[5];
    const float* b_rec_inpgate  = (const float*)d_in[6];
    const float* w_mem_inpgate  = (const float*)d_in[7];
    const float* b_mem_inpgate  = (const float*)d_in[8];
    const float* w_inp          = (const float*)d_in[9];
    const float* b_inp          = (const float*)d_in[10];
    const float* w_rec_inp      = (const float*)d_in[11];
    const float* b_rec_inp      = (const float*)d_in[12];
    const float* w_readgate     = (const float*)d_in[13];
    const float* b_readgate     = (const float*)d_in[14];
    const float* w_rec_readgate = (const float*)d_in[15];
    const float* b_rec_readgate = (const float*)d_in[16];
    const float* w_mem_readgate = (const float*)d_in[17];
    const float* b_mem_readgate = (const float*)d_in[18];
    const float* w_decoder      = (const float*)d_in[19];
    const float* b_decoder      = (const float*)d_in[20];
    float* out = (float*)d_out;

    void *pA, *pB, *pC, *pD, *pax, *pay, *pw0, *pw1, *pw2;
    cudaGetSymbolAddress(&pA, g_preA); cudaGetSymbolAddress(&pB, g_preB);
    cudaGetSymbolAddress(&pC, g_preC); cudaGetSymbolAddress(&pD, g_dec);
    cudaGetSymbolAddress(&pax, g_ax);  cudaGetSymbolAddress(&pay, g_ay);
    cudaGetSymbolAddress(&pw0, g_w0);  cudaGetSymbolAddress(&pw1, g_w1);
    cudaGetSymbolAddress(&pw2, g_w2);
    float* preA = (float*)pA;  float* preB = (float*)pB;
    float* preC = (float*)pC;  float* dec  = (float*)pD;
    __half* ax = (__half*)pax; __half* ay = (__half*)pay;
    __half* w0h = (__half*)pw0; __half* w1h = (__half*)pw1; __half* w2h = (__half*)pw2;

    cudaFuncSetAttribute(gemm_fp16, cudaFuncAttributeMaxDynamicSharedMemorySize, GEMM_SMEM);

    const int nA4 = (BDIM * KDIM) / 4;
    const int nW4 = (DDIM * KDIM) / 4;
    const dim3 GRID1(DDIM / CTAN, BDIM / CTAM, 1);  // 16 x 32
    const dim3 GRID2(DDIM / CTAN, BDIM / CTAM, 2);
    const dim3 GRID3(DDIM / CTAN, BDIM / CTAM, 3);

    // 1) flags + convert x (fused)
    reset_flags_kernel<<<1, 1>>>();
    scanconv_kernel<<<2048, 256>>>((const float4*)x, (uint2*)ax,
                                   (const float4*)mem0, (const float4*)out0);

    // 2) convert the three x-side weights (ungated)
    {
        ConvBatch cb = {};
        cb.src[0] = (const float4*)w_inp;      cb.dst[0] = (uint2*)w0h; cb.n4[0] = nW4; cb.flagsel[0] = 0;
        cb.src[1] = (const float4*)w_inpgate;  cb.dst[1] = (uint2*)w1h; cb.n4[1] = nW4; cb.flagsel[1] = 0;
        cb.src[2] = (const float4*)w_readgate; cb.dst[2] = (uint2*)w2h; cb.n4[2] = nW4; cb.flagsel[2] = 0;
        conv_batch_kernel<<<dim3(512, 1, 3), 256>>>(cb);
    }

    // 3) GEMM batch: preA (always), preC (mem gated)
    {
        GemmBatch gb = {};
        gb.W[0] = w0h; gb.C[0] = preA; gb.b0[0] = b_inp;      gb.b1[0] = b_rec_inp;      gb.flagsel[0] = 0;
        gb.W[1] = w2h; gb.C[1] = preC; gb.b0[1] = b_readgate; gb.b1[1] = b_mem_readgate; gb.b2[1] = b_rec_readgate; gb.flagsel[1] = 1;
        gb.accum = 0;
        gemm_fp16<<<GRID2, 256, GEMM_SMEM>>>(ax, gb, 0, nullptr, nullptr, nullptr);
    }

    // 4) preB GEMM with fused final epilogue (fast path writes `out` directly)
    {
        GemmBatch gb = {};
        gb.W[0] = w1h; gb.C[0] = preB;
        gb.b0[0] = b_inpgate; gb.b1[0] = b_mem_inpgate; gb.b2[0] = b_rec_inpgate;
        gb.flagsel[0] = 0; gb.accum = 0;
        gemm_fp16<<<GRID1, 256, GEMM_SMEM>>>(ax, gb, 1, preA, out, b_decoder);
    }

    // 5) out0 recurrent terms  [out0 != 0]
    {
        ConvBatch cb = {};
        cb.src[0] = (const float4*)out0;            cb.dst[0] = (uint2*)ay;  cb.n4[0] = nA4; cb.flagsel[0] = 2;
        cb.src[1] = (const float4*)w_rec_inp;       cb.dst[1] = (uint2*)w0h; cb.n4[1] = nW4; cb.flagsel[1] = 2;
        cb.src[2] = (const float4*)w_rec_inpgate;   cb.dst[2] = (uint2*)w1h; cb.n4[2] = nW4; cb.flagsel[2] = 2;
        cb.src[3] = (const float4*)w_rec_readgate;  cb.dst[3] = (uint2*)w2h; cb.n4[3] = nW4; cb.flagsel[3] = 3;
        conv_batch_kernel<<<dim3(512, 1, 4), 256>>>(cb);
    }
    {
        GemmBatch gb = {};
        gb.W[0] = w0h; gb.C[0] = preA; gb.flagsel[0] = 2;
        gb.W[1] = w1h; gb.C[1] = preB; gb.flagsel[1] = 2;
        gb.W[2] = w2h; gb.C[2] = preC; gb.flagsel[2] = 3;
        gb.accum = 1;
        gemm_fp16<<<GRID3, 256, GEMM_SMEM>>>(ay, gb, 0, nullptr, nullptr, nullptr);
    }

    // 6) mem0 terms  [mem0 != 0]
    {
        ConvBatch cb = {};
        cb.src[0] = (const float4*)mem0;            cb.dst[0] = (uint2*)ay;  cb.n4[0] = nA4; cb.flagsel[0] = 1;
        cb.src[1] = (const float4*)w_mem_inpgate;   cb.dst[1] = (uint2*)w0h; cb.n4[1] = nW4; cb.flagsel[1] = 1;
        cb.src[2] = (const float4*)w_mem_readgate;  cb.dst[2] = (uint2*)w1h; cb.n4[2] = nW4; cb.flagsel[2] = 1;
        conv_batch_kernel<<<dim3(512, 1, 3), 256>>>(cb);
    }
    {
        GemmBatch gb = {};
        gb.W[0] = w0h; gb.C[0] = preB; gb.flagsel[0] = 1;
        gb.W[1] = w1h; gb.C[1] = preC; gb.flagsel[1] = 1;
        gb.accum = 1;
        gemm_fp16<<<GRID2, 256, GEMM_SMEM>>>(ay, gb, 0, nullptr, nullptr, nullptr);
    }

    // 7) ay = fp16(sigmoid(preC)*mem0), convert w_decoder, decoder GEMM  [mem0 != 0]
    rgconv_kernel<<<2048, 256>>>((const float4*)mem0, (uint2*)ay);
    {
        ConvBatch cb = {};
        cb.src[0] = (const float4*)w_decoder; cb.dst[0] = (uint2*)w0h; cb.n4[0] = nW4; cb.flagsel[0] = 1;
        conv_batch_kernel<<<dim3(512, 1, 1), 256>>>(cb);
    }
    {
        GemmBatch gb = {};
        gb.W[0] = w0h; gb.C[0] = dec; gb.b0[0] = b_decoder; gb.flagsel[0] = 1;
        gb.accum = 0;
        gemm_fp16<<<GRID1, 256, GEMM_SMEM>>>(ay, gb, 0, nullptr, nullptr, nullptr);
    }

    // 8) slow-path final (gated off when both states are zero)
    final_kernel<<<2048, 256>>>(out, b_decoder);
}